// round 3
// baseline (speedup 1.0000x reference)
#include <cuda_runtime.h>
#include <cuda_bf16.h>
#include <math.h>

// ---------------------------------------------------------------------------
// TreeEncoder, fp32, FFMA2 (fma.rn.f32x2) register-blocked GEMMs.
// 128x128 block tile / 256 threads / 8x8 micro-tile / BK=16 / double-buffered.
// conv fuses child->parent pooling into its epilogue; emb+LN is one launch.
// ---------------------------------------------------------------------------

#define MAX_DEPTH 9
#define TOTAL 349525          // sum 4^d, d=0..9
#define OFF9  87381           // offset of depth 9
#define XCOLS 48              // 40 real input cols, padded to 48

__constant__ int c_off[11] = {0,1,5,21,85,341,1365,5461,21845,87381,349525};
// emb merged-launch: blocks per depth = ceil(size/128): 1,1,1,1,2,8,32,128,512,2048
__constant__ int c_embcum[11] = {0,1,2,3,4,6,14,46,174,686,2734};

static const int h_off[11]  = {0,1,5,21,85,341,1365,5461,21845,87381,349525};
static const int h_size[10] = {1,4,16,64,256,1024,4096,16384,65536,262144};

// ---------------- static scratch (no runtime allocation) -------------------
__device__ float HBUF[TOTAL * 128];          // h after in_proj (+ pooling adds)
__device__ float HCBUF[OFF9 * 128];          // conv outputs, depths 1..8
__device__ float XBUF[TOTAL * XCOLS];        // padded pos-encoded inputs
__device__ float WT_IN[XCOLS * 128];         // in_proj_W^T (k-major), zero-padded
__device__ float WT_CONV[10 * 1152 * 128];   // conv_W^T per depth (k-major)
__device__ float WT_EMB[10 * 128 * 128];     // emb_W^T per depth (k-major)

// ---------------- Morton helpers -------------------------------------------
__device__ __forceinline__ unsigned mi_interleave(unsigned x) {
    x &= 0xFFFFu;
    x = (x | (x << 8)) & 0x00FF00FFu;
    x = (x | (x << 4)) & 0x0F0F0F0Fu;
    x = (x | (x << 2)) & 0x33333333u;
    x = (x | (x << 1)) & 0x55555555u;
    return x;
}
__device__ __forceinline__ unsigned mi_deinterleave(unsigned x) {
    x &= 0x55555555u;
    x = (x | (x >> 1)) & 0x33333333u;
    x = (x | (x >> 2)) & 0x0F0F0F0Fu;
    x = (x | (x >> 4)) & 0x00FF00FFu;
    x = (x | (x >> 8)) & 0xFFFFu;
    return x;
}

// ---------------- packed f32x2 helpers --------------------------------------
__device__ __forceinline__ unsigned long long f32x2_dup(float a) {
    unsigned long long r;
    asm("mov.b64 %0, {%1, %1};" : "=l"(r) : "f"(a));
    return r;
}
__device__ __forceinline__ void f32x2_fma(unsigned long long& d,
                                          unsigned long long a,
                                          unsigned long long b) {
    asm("fma.rn.f32x2 %0, %1, %2, %0;" : "+l"(d) : "l"(a), "l"(b));
}
__device__ __forceinline__ void f32x2_unpack(unsigned long long v, float& lo, float& hi) {
    asm("mov.b64 {%0, %1}, %2;" : "=f"(lo), "=f"(hi) : "l"(v));
}

// ---------------- shared-tile compute: 16 k-steps, 8x8 micro-tile ----------
__device__ __forceinline__ void mma16(const float* As, const float* Bs,
                                      int ty, int tx,
                                      unsigned long long (&acc)[8][4]) {
#pragma unroll
    for (int kk = 0; kk < 16; kk++) {
        const float* ar = As + kk * 128 + ty * 8;
        const float* br = Bs + kk * 128 + tx * 8;
        float4 a0 = *(const float4*)ar;
        float4 a1 = *(const float4*)(ar + 4);
        ulonglong2 bA = *(const ulonglong2*)br;
        ulonglong2 bB = *(const ulonglong2*)(br + 4);
        unsigned long long bp0 = bA.x, bp1 = bA.y, bp2 = bB.x, bp3 = bB.y;
        float av[8] = {a0.x, a0.y, a0.z, a0.w, a1.x, a1.y, a1.z, a1.w};
#pragma unroll
        for (int ri = 0; ri < 8; ri++) {
            unsigned long long ap = f32x2_dup(av[ri]);
            f32x2_fma(acc[ri][0], ap, bp0);
            f32x2_fma(acc[ri][1], ap, bp1);
            f32x2_fma(acc[ri][2], ap, bp2);
            f32x2_fma(acc[ri][3], ap, bp3);
        }
    }
}

// ---------------- weight transposition --------------------------------------
#define PREP_TOTAL (XCOLS*128 + 10*1152*128 + 10*128*128)

__global__ void prep_kernel(const float* __restrict__ in_proj_W,
                            const float* __restrict__ conv_W,
                            const float* __restrict__ emb_W) {
    int i = blockIdx.x * blockDim.x + threadIdx.x;
    if (i < XCOLS * 128) {
        int c = i / 128, j = i % 128;
        WT_IN[i] = (c < 40) ? in_proj_W[j * 40 + c] : 0.f;
        return;
    }
    i -= XCOLS * 128;
    if (i < 10 * 1152 * 128) {
        int d = i / (1152 * 128);
        int r = i % (1152 * 128);
        int k = r / 128, j = r % 128;
        WT_CONV[d * 1152 * 128 + r] = conv_W[(d * 128 + j) * 1152 + k];
        return;
    }
    i -= 10 * 1152 * 128;
    if (i < 10 * 128 * 128) {
        int d = i / 16384;
        int r = i % 16384;
        int c = r / 128, j = r % 128;
        WT_EMB[d * 16384 + r] = emb_W[(d * 128 + j) * 128 + c];
    }
}

// ---------------- positional encoding ---------------------------------------
__global__ void posenc_kernel(const float* __restrict__ feats) {
    int i = blockIdx.x * blockDim.x + threadIdx.x;
    if (i >= TOTAL * XCOLS) return;
    int node = i / XCOLS, c = i % XCOLS;
    float v = 0.f;
    if (c < 40) {
        int d = 0;
        while (node >= c_off[d + 1]) d++;
        int local = node - c_off[d];
        if (c == 0) {
            v = feats[node];
        } else {
            unsigned ix = mi_deinterleave((unsigned)local);
            unsigned iy = mi_deinterleave((unsigned)local >> 1);
            float inv = 1.f / (float)(1 << d);
            float px = ((float)ix + 0.5f) * inv;
            float py = ((float)iy + 0.5f) * inv;
            float pd = (float)d * (1.f / 9.f);
            if (c == 1)      v = px;
            else if (c == 2) v = py;
            else if (c == 3) v = pd;
            else {
                int e = c - 4;
                int dim = e / 12, rem = e % 12;
                int f = rem % 6;
                float p = (dim == 0) ? px : (dim == 1) ? py : pd;
                float t = p * (float)(1 << f);
                float tr = t - rintf(t);
                v = (rem >= 6) ? cospif(2.f * tr) : sinpif(2.f * tr);
            }
        }
    }
    XBUF[i] = v;
}

// ---------------- pooling d9 -> d8 (float4) ---------------------------------
__global__ void pool9_kernel() {
    int u = blockIdx.x * blockDim.x + threadIdx.x;   // 65536 parents * 32 quads
    if (u >= 65536 * 32) return;
    int p = u >> 5, c4 = (u & 31) * 4;
    const float* s = HBUF + (size_t)(OFF9 + p * 4) * 128 + c4;
    float4 s0 = *(const float4*)(s);
    float4 s1 = *(const float4*)(s + 128);
    float4 s2 = *(const float4*)(s + 256);
    float4 s3 = *(const float4*)(s + 384);
    float* dp = HBUF + (size_t)(21845 + p) * 128 + c4;
    float4 d0 = *(float4*)dp;
    d0.x += 0.25f * (s0.x + s1.x + s2.x + s3.x);
    d0.y += 0.25f * (s0.y + s1.y + s2.y + s3.y);
    d0.z += 0.25f * (s0.z + s1.z + s2.z + s3.z);
    d0.w += 0.25f * (s0.w + s1.w + s2.w + s3.w);
    *(float4*)dp = d0;
}

// ---------------- in_proj GEMM: XBUF[N,48] @ WT_IN -> HBUF ------------------
__global__ __launch_bounds__(256, 2)
void inproj_gemm(const float* __restrict__ bias) {
    __shared__ float As[2][16 * 128];
    __shared__ float Bs[2][16 * 128];
    int t = threadIdx.x;
    int base = blockIdx.x * 128;
    int tx = t & 15, ty = t >> 4;
    int r0 = t >> 2, kq = t & 3;          // A slots: rows r0, r0+64
    int kb = t >> 4, jb = (t & 15) * 8;   // B slots: 2 float4 at (kb, jb)

    unsigned long long acc[8][4];
#pragma unroll
    for (int ri = 0; ri < 8; ri++)
#pragma unroll
        for (int cj = 0; cj < 4; cj++) acc[ri][cj] = 0ULL;

    float4 ra[2], rb[2];
    const int KT = 3;   // 48 / 16
    // prologue load (k0 = 0)
#pragma unroll
    for (int i = 0; i < 2; i++) {
        int node = base + r0 + i * 64;
        ra[i] = make_float4(0.f, 0.f, 0.f, 0.f);
        if (node < TOTAL)
            ra[i] = *(const float4*)&XBUF[(size_t)node * XCOLS + kq * 4];
        rb[i] = *(const float4*)&WT_IN[kb * 128 + jb + i * 4];
    }
    for (int it = 0; it < KT; it++) {
        int buf = it & 1;
        float* as = As[buf];
        float* bs = Bs[buf];
        as[(kq * 4 + 0) * 128 + r0] = ra[0].x;
        as[(kq * 4 + 1) * 128 + r0] = ra[0].y;
        as[(kq * 4 + 2) * 128 + r0] = ra[0].z;
        as[(kq * 4 + 3) * 128 + r0] = ra[0].w;
        as[(kq * 4 + 0) * 128 + r0 + 64] = ra[1].x;
        as[(kq * 4 + 1) * 128 + r0 + 64] = ra[1].y;
        as[(kq * 4 + 2) * 128 + r0 + 64] = ra[1].z;
        as[(kq * 4 + 3) * 128 + r0 + 64] = ra[1].w;
        *(float4*)&bs[kb * 128 + jb] = rb[0];
        *(float4*)&bs[kb * 128 + jb + 4] = rb[1];
        __syncthreads();
        if (it + 1 < KT) {
            int k0 = (it + 1) * 16;
#pragma unroll
            for (int i = 0; i < 2; i++) {
                int node = base + r0 + i * 64;
                ra[i] = make_float4(0.f, 0.f, 0.f, 0.f);
                if (node < TOTAL)
                    ra[i] = *(const float4*)&XBUF[(size_t)node * XCOLS + k0 + kq * 4];
                rb[i] = *(const float4*)&WT_IN[(k0 + kb) * 128 + jb + i * 4];
            }
        }
        mma16(As[buf], Bs[buf], ty, tx, acc);
    }

    float4 b0 = *(const float4*)&bias[tx * 8];
    float4 b1 = *(const float4*)&bias[tx * 8 + 4];
    float bb[8] = {b0.x, b0.y, b0.z, b0.w, b1.x, b1.y, b1.z, b1.w};
#pragma unroll
    for (int ri = 0; ri < 8; ri++) {
        int node = base + ty * 8 + ri;
        if (node >= TOTAL) continue;
        float o[8];
#pragma unroll
        for (int cj = 0; cj < 4; cj++)
            f32x2_unpack(acc[ri][cj], o[2 * cj], o[2 * cj + 1]);
        float4 v0 = make_float4(o[0] + bb[0], o[1] + bb[1], o[2] + bb[2], o[3] + bb[3]);
        float4 v1 = make_float4(o[4] + bb[4], o[5] + bb[5], o[6] + bb[6], o[7] + bb[7]);
        float* dst = &HBUF[(size_t)node * 128 + tx * 8];
        *(float4*)dst = v0;
        *(float4*)(dst + 4) = v1;
    }
}

// ---------------- quadconv (implicit GEMM, fused child->parent pool) --------
__global__ __launch_bounds__(256, 2)
void conv_kernel(int depth, int off, int off_prev, int N,
                 const float* __restrict__ conv_b) {
    __shared__ float As[2][16 * 128];
    __shared__ float Bs[2][16 * 128];
    __shared__ int nbs[9][128];
    int t = threadIdx.x;
    int base = blockIdx.x * 128;
    int res = 1 << depth;
    int tx = t & 15, ty = t >> 4;
    int r0 = t >> 2, kq = t & 3;
    int kb = t >> 4, jb = (t & 15) * 8;

    for (int e = t; e < 9 * 128; e += 256) {
        int m = e >> 7, r = e & 127;
        int node = base + r;
        int val = -1;
        if (node < N) {
            unsigned ix = mi_deinterleave((unsigned)node);
            unsigned iy = mi_deinterleave((unsigned)node >> 1);
            int dx = m % 3 - 1, dy = m / 3 - 1;
            int nx = (int)ix + dx, ny = (int)iy + dy;
            if (nx >= 0 && nx < res && ny >= 0 && ny < res)
                val = (int)(mi_interleave((unsigned)nx) | (mi_interleave((unsigned)ny) << 1));
        }
        nbs[m][r] = val;
    }
    __syncthreads();

    const float* Wt = WT_CONV + (size_t)depth * 1152 * 128;

    unsigned long long acc[8][4];
#pragma unroll
    for (int ri = 0; ri < 8; ri++)
#pragma unroll
        for (int cj = 0; cj < 4; cj++) acc[ri][cj] = 0ULL;

    float4 ra[2], rb[2];
    const int KT = 72;   // 1152 / 16
    {
        int m = 0, c0 = kq * 4;
#pragma unroll
        for (int i = 0; i < 2; i++) {
            int nbi = nbs[m][r0 + i * 64];
            ra[i] = make_float4(0.f, 0.f, 0.f, 0.f);
            if (nbi >= 0)
                ra[i] = *(const float4*)&HBUF[(size_t)(off + nbi) * 128 + c0];
            rb[i] = *(const float4*)&Wt[(size_t)kb * 128 + jb + i * 4];
        }
    }
    for (int it = 0; it < KT; it++) {
        int buf = it & 1;
        float* as = As[buf];
        float* bs = Bs[buf];
        as[(kq * 4 + 0) * 128 + r0] = ra[0].x;
        as[(kq * 4 + 1) * 128 + r0] = ra[0].y;
        as[(kq * 4 + 2) * 128 + r0] = ra[0].z;
        as[(kq * 4 + 3) * 128 + r0] = ra[0].w;
        as[(kq * 4 + 0) * 128 + r0 + 64] = ra[1].x;
        as[(kq * 4 + 1) * 128 + r0 + 64] = ra[1].y;
        as[(kq * 4 + 2) * 128 + r0 + 64] = ra[1].z;
        as[(kq * 4 + 3) * 128 + r0 + 64] = ra[1].w;
        *(float4*)&bs[kb * 128 + jb] = rb[0];
        *(float4*)&bs[kb * 128 + jb + 4] = rb[1];
        __syncthreads();
        if (it + 1 < KT) {
            int k0 = (it + 1) * 16;
            int m = k0 >> 7;
            int c0 = (k0 & 127) + kq * 4;
#pragma unroll
            for (int i = 0; i < 2; i++) {
                int nbi = nbs[m][r0 + i * 64];
                ra[i] = make_float4(0.f, 0.f, 0.f, 0.f);
                if (nbi >= 0)
                    ra[i] = *(const float4*)&HBUF[(size_t)(off + nbi) * 128 + c0];
                rb[i] = *(const float4*)&Wt[(size_t)(k0 + kb) * 128 + jb + i * 4];
            }
        }
        mma16(As[buf], Bs[buf], ty, tx, acc);
    }

    float4 b0 = *(const float4*)&conv_b[depth * 128 + tx * 8];
    float4 b1 = *(const float4*)&conv_b[depth * 128 + tx * 8 + 4];
    float bb[8] = {b0.x, b0.y, b0.z, b0.w, b1.x, b1.y, b1.z, b1.w};

    float ps[2][8];
#pragma unroll
    for (int g = 0; g < 2; g++)
#pragma unroll
        for (int u = 0; u < 8; u++) ps[g][u] = 0.f;

#pragma unroll
    for (int ri = 0; ri < 8; ri++) {
        int node = base + ty * 8 + ri;
        float o[8];
#pragma unroll
        for (int cj = 0; cj < 4; cj++)
            f32x2_unpack(acc[ri][cj], o[2 * cj], o[2 * cj + 1]);
#pragma unroll
        for (int u = 0; u < 8; u++) {
            o[u] = fmaxf(o[u] + bb[u], 0.f);
            ps[ri >> 2][u] += o[u];
        }
        if (node < N) {
            float* dst = &HCBUF[(size_t)(off + node) * 128 + tx * 8];
            *(float4*)dst = make_float4(o[0], o[1], o[2], o[3]);
            *(float4*)(dst + 4) = make_float4(o[4], o[5], o[6], o[7]);
        }
    }
    // fused pooling: rows ty*8 .. ty*8+7 form 2 complete Morton sibling groups
#pragma unroll
    for (int g = 0; g < 2; g++) {
        int first = base + ty * 8 + g * 4;
        if (first + 3 < N) {
            int pa = first >> 2;
            float* dst = &HBUF[(size_t)(off_prev + pa) * 128 + tx * 8];
            float4 d0 = *(float4*)dst;
            float4 d1 = *(float4*)(dst + 4);
            d0.x += 0.25f * ps[g][0]; d0.y += 0.25f * ps[g][1];
            d0.z += 0.25f * ps[g][2]; d0.w += 0.25f * ps[g][3];
            d1.x += 0.25f * ps[g][4]; d1.y += 0.25f * ps[g][5];
            d1.z += 0.25f * ps[g][6]; d1.w += 0.25f * ps[g][7];
            *(float4*)dst = d0;
            *(float4*)(dst + 4) = d1;
        }
    }
}

// ---------------- emb GEMM + fused LayerNorm, all depths in one launch ------
__global__ __launch_bounds__(256, 2)
void emb_all_kernel(const float* __restrict__ emb_b,
                    const float* __restrict__ ln_g,
                    const float* __restrict__ ln_b,
                    const float* __restrict__ gain_all,
                    float* __restrict__ out) {
    __shared__ float As[2][16 * 128];
    __shared__ float Bs[2][16 * 128];
    int b = blockIdx.x;
    int depth = 0;
    while (b >= c_embcum[depth + 1]) depth++;
    int base = (b - c_embcum[depth]) * 128;
    int off = c_off[depth];
    int N = c_off[depth + 1] - off;
    const float* src = (depth >= 1 && depth <= 8) ? HCBUF : HBUF;
    const float* Wt = WT_EMB + (size_t)depth * 16384;

    int t = threadIdx.x;
    int tx = t & 15, ty = t >> 4;
    int r0 = t >> 2, kq = t & 3;
    int kb = t >> 4, jb = (t & 15) * 8;

    unsigned long long acc[8][4];
#pragma unroll
    for (int ri = 0; ri < 8; ri++)
#pragma unroll
        for (int cj = 0; cj < 4; cj++) acc[ri][cj] = 0ULL;

    float4 ra[2], rb[2];
    const int KT = 8;   // 128 / 16
#pragma unroll
    for (int i = 0; i < 2; i++) {
        int node = base + r0 + i * 64;
        ra[i] = make_float4(0.f, 0.f, 0.f, 0.f);
        if (node < N)
            ra[i] = *(const float4*)&src[(size_t)(off + node) * 128 + kq * 4];
        rb[i] = *(const float4*)&Wt[(size_t)kb * 128 + jb + i * 4];
    }
    for (int it = 0; it < KT; it++) {
        int buf = it & 1;
        float* as = As[buf];
        float* bs = Bs[buf];
        as[(kq * 4 + 0) * 128 + r0] = ra[0].x;
        as[(kq * 4 + 1) * 128 + r0] = ra[0].y;
        as[(kq * 4 + 2) * 128 + r0] = ra[0].z;
        as[(kq * 4 + 3) * 128 + r0] = ra[0].w;
        as[(kq * 4 + 0) * 128 + r0 + 64] = ra[1].x;
        as[(kq * 4 + 1) * 128 + r0 + 64] = ra[1].y;
        as[(kq * 4 + 2) * 128 + r0 + 64] = ra[1].z;
        as[(kq * 4 + 3) * 128 + r0 + 64] = ra[1].w;
        *(float4*)&bs[kb * 128 + jb] = rb[0];
        *(float4*)&bs[kb * 128 + jb + 4] = rb[1];
        __syncthreads();
        if (it + 1 < KT) {
            int k0 = (it + 1) * 16;
#pragma unroll
            for (int i = 0; i < 2; i++) {
                int node = base + r0 + i * 64;
                ra[i] = make_float4(0.f, 0.f, 0.f, 0.f);
                if (node < N)
                    ra[i] = *(const float4*)&src[(size_t)(off + node) * 128 + k0 + kq * 4];
                rb[i] = *(const float4*)&Wt[(size_t)(k0 + kb) * 128 + jb + i * 4];
            }
        }
        mma16(As[buf], Bs[buf], ty, tx, acc);
    }

    // epilogue: LN across 128 cols; each row's cols live on 16 lanes (tx bits)
    float4 e0 = *(const float4*)&emb_b[depth * 128 + tx * 8];
    float4 e1 = *(const float4*)&emb_b[depth * 128 + tx * 8 + 4];
    float4 g0 = *(const float4*)&ln_g[depth * 128 + tx * 8];
    float4 g1 = *(const float4*)&ln_g[depth * 128 + tx * 8 + 4];
    float4 l0 = *(const float4*)&ln_b[depth * 128 + tx * 8];
    float4 l1 = *(const float4*)&ln_b[depth * 128 + tx * 8 + 4];
    float eb[8] = {e0.x, e0.y, e0.z, e0.w, e1.x, e1.y, e1.z, e1.w};
    float lg[8] = {g0.x, g0.y, g0.z, g0.w, g1.x, g1.y, g1.z, g1.w};
    float lb[8] = {l0.x, l0.y, l0.z, l0.w, l1.x, l1.y, l1.z, l1.w};
    float gain = gain_all[depth];

#pragma unroll
    for (int ri = 0; ri < 8; ri++) {
        float z[8];
#pragma unroll
        for (int cj = 0; cj < 4; cj++)
            f32x2_unpack(acc[ri][cj], z[2 * cj], z[2 * cj + 1]);
        float s = 0.f;
#pragma unroll
        for (int u = 0; u < 8; u++) { z[u] += eb[u]; s += z[u]; }
#pragma unroll
        for (int o = 8; o > 0; o >>= 1) s += __shfl_xor_sync(0xFFFFFFFFu, s, o);
        float mu = s * (1.f / 128.f);
        float q = 0.f;
#pragma unroll
        for (int u = 0; u < 8; u++) { z[u] -= mu; q += z[u] * z[u]; }
#pragma unroll
        for (int o = 8; o > 0; o >>= 1) q += __shfl_xor_sync(0xFFFFFFFFu, q, o);
        float rs = rsqrtf(q * (1.f / 128.f) + 1e-5f);
        int node = base + ty * 8 + ri;
        if (node < N) {
            float o0[8];
#pragma unroll
            for (int u = 0; u < 8; u++)
                o0[u] = gain * (z[u] * rs * lg[u] + lb[u]);
            float* dst = &out[(size_t)(off + node) * 128 + tx * 8];
            *(float4*)dst = make_float4(o0[0], o0[1], o0[2], o0[3]);
            *(float4*)(dst + 4) = make_float4(o0[4], o0[5], o0[6], o0[7]);
        }
    }
}

// ---------------------------------------------------------------------------
extern "C" void kernel_launch(void* const* d_in, const int* in_sizes, int n_in,
                              void* d_out, int out_size) {
    const float* feats     = (const float*)d_in[0];
    const float* in_proj_W = (const float*)d_in[1];
    const float* in_proj_b = (const float*)d_in[2];
    const float* conv_W    = (const float*)d_in[3];
    const float* conv_b    = (const float*)d_in[4];
    const float* emb_W     = (const float*)d_in[5];
    const float* emb_b     = (const float*)d_in[6];
    const float* ln_g      = (const float*)d_in[7];
    const float* ln_b      = (const float*)d_in[8];
    const float* gain      = (const float*)d_in[9];
    float* out = (float*)d_out;

    prep_kernel<<<(PREP_TOTAL + 255) / 256, 256>>>(in_proj_W, conv_W, emb_W);
    posenc_kernel<<<(TOTAL * XCOLS + 255) / 256, 256>>>(feats);
    inproj_gemm<<<(TOTAL + 127) / 128, 256>>>(in_proj_b);

    pool9_kernel<<<(65536 * 32 + 255) / 256, 256>>>();
    for (int dc = 8; dc >= 1; dc--) {
        conv_kernel<<<(h_size[dc] + 127) / 128, 256>>>(dc, h_off[dc], h_off[dc - 1],
                                                       h_size[dc], conv_b);
    }
    emb_all_kernel<<<2734, 256>>>(emb_b, ln_g, ln_b, gain, out);
}

// round 6
// speedup vs baseline: 2.0428x; 2.0428x over previous
#include <cuda_runtime.h>
#include <cuda_bf16.h>
#include <math.h>
#include <stdint.h>

// ---------------------------------------------------------------------------
// TreeEncoder via mma.sync bf16 split-GEMM (hi/lo, 3 products, fp32 accum).
// Base sm_100-compatible (no tcgen05). Block tile 64x128, 8 warps (2Mx4N),
// warp tile 32x32, K-chunk 32, double-buffered padded smem + ldmatrix.
// ---------------------------------------------------------------------------

#define MAX_DEPTH 9
#define TOTAL 349525
#define OFF9  87381
#define XCOLS 48

__constant__ int c_off[11] = {0,1,5,21,85,341,1365,5461,21845,87381,349525};
__constant__ int c_embcum[11] = {0,1,2,3,4,8,24,88,344,1368,5464};

static const int h_off[11]  = {0,1,5,21,85,341,1365,5461,21845,87381,349525};
static const int h_size[10] = {1,4,16,64,256,1024,4096,16384,65536,262144};

// ---------------- static scratch -------------------------------------------
__device__ float HBUF[TOTAL * 128];
__device__ float HCBUF[OFF9 * 128];
__device__ float XBUF[TOTAL * XCOLS];
// prepacked bf16 hi/lo weight chunk images: [tile][j=128][k=32]
__device__ __align__(16) __nv_bfloat16 WIH[2*4096],     WIL[2*4096];
__device__ __align__(16) __nv_bfloat16 WCH[10*36*4096], WCL[10*36*4096];
__device__ __align__(16) __nv_bfloat16 WEH[10*4*4096],  WEL[10*4*4096];

// ---------------- Morton helpers -------------------------------------------
__device__ __forceinline__ unsigned mi_interleave(unsigned x) {
    x &= 0xFFFFu;
    x = (x | (x << 8)) & 0x00FF00FFu;
    x = (x | (x << 4)) & 0x0F0F0F0Fu;
    x = (x | (x << 2)) & 0x33333333u;
    x = (x | (x << 1)) & 0x55555555u;
    return x;
}
__device__ __forceinline__ unsigned mi_deinterleave(unsigned x) {
    x &= 0x55555555u;
    x = (x | (x >> 1)) & 0x33333333u;
    x = (x | (x >> 2)) & 0x0F0F0F0Fu;
    x = (x | (x >> 4)) & 0x00FF00FFu;
    x = (x | (x >> 8)) & 0xFFFFu;
    return x;
}

// ---------------- PTX helpers ----------------------------------------------
__device__ __forceinline__ uint32_t smem_u32(const void* p) {
    uint32_t a;
    asm("{ .reg .u64 tmp; cvta.to.shared.u64 tmp, %1; cvt.u32.u64 %0, tmp; }"
        : "=r"(a) : "l"(p));
    return a;
}
__device__ __forceinline__ void ldsm4(uint32_t* r, uint32_t addr) {
    asm volatile("ldmatrix.sync.aligned.m8n8.x4.shared.b16 {%0,%1,%2,%3}, [%4];"
        : "=r"(r[0]), "=r"(r[1]), "=r"(r[2]), "=r"(r[3]) : "r"(addr));
}
__device__ __forceinline__ void mma_bf16(float* d, const uint32_t* a, const uint32_t* b) {
    asm volatile(
        "mma.sync.aligned.m16n8k16.row.col.f32.bf16.bf16.f32 "
        "{%0,%1,%2,%3}, {%4,%5,%6,%7}, {%8,%9}, {%0,%1,%2,%3};"
        : "+f"(d[0]), "+f"(d[1]), "+f"(d[2]), "+f"(d[3])
        : "r"(a[0]), "r"(a[1]), "r"(a[2]), "r"(a[3]), "r"(b[0]), "r"(b[1]));
}

// ---------------- split fp32 -> bf16 hi/lo, store 8 elems -------------------
__device__ __forceinline__ void split_store(char* ah, char* al, int off,
                                            float4 v0, float4 v1) {
    __nv_bfloat162 h0 = __float22bfloat162_rn(make_float2(v0.x, v0.y));
    __nv_bfloat162 h1 = __float22bfloat162_rn(make_float2(v0.z, v0.w));
    __nv_bfloat162 h2 = __float22bfloat162_rn(make_float2(v1.x, v1.y));
    __nv_bfloat162 h3 = __float22bfloat162_rn(make_float2(v1.z, v1.w));
    float2 f0 = __bfloat1622float2(h0), f1 = __bfloat1622float2(h1);
    float2 f2 = __bfloat1622float2(h2), f3 = __bfloat1622float2(h3);
    __nv_bfloat162 l0 = __float22bfloat162_rn(make_float2(v0.x - f0.x, v0.y - f0.y));
    __nv_bfloat162 l1 = __float22bfloat162_rn(make_float2(v0.z - f1.x, v0.w - f1.y));
    __nv_bfloat162 l2 = __float22bfloat162_rn(make_float2(v1.x - f2.x, v1.y - f2.y));
    __nv_bfloat162 l3 = __float22bfloat162_rn(make_float2(v1.z - f3.x, v1.w - f3.y));
    *(uint4*)(ah + off) = make_uint4(*(unsigned*)&h0, *(unsigned*)&h1,
                                     *(unsigned*)&h2, *(unsigned*)&h3);
    *(uint4*)(al + off) = make_uint4(*(unsigned*)&l0, *(unsigned*)&l1,
                                     *(unsigned*)&l2, *(unsigned*)&l3);
}

// ---------------- smem buffer geometry --------------------------------------
// per-buffer: Ah[64*80] Al[64*80] Bh[128*80] Bl[128*80] = 30720 bytes, x2 bufs
#define BUFB 30720
#define DSM_BYTES (2 * BUFB)

// ---------------- shared compute: one 32-k chunk ----------------------------
__device__ __forceinline__ void compute_chunk(uint32_t sb, int warp_m, int warp_n,
                                              int a_row, int a_byte,
                                              int b_row, int b_byte,
                                              float (*acc)[4][4]) {
    uint32_t Ah = sb, Al = sb + 5120, Bh = sb + 10240, Bl = sb + 20480;
#pragma unroll
    for (int kt = 0; kt < 2; kt++) {
        uint32_t ah[2][4], al[2][4];
#pragma unroll
        for (int mt = 0; mt < 2; mt++) {
            uint32_t ao = (uint32_t)((warp_m * 32 + mt * 16 + a_row) * 80 + kt * 32 + a_byte);
            ldsm4(ah[mt], Ah + ao);
            ldsm4(al[mt], Al + ao);
        }
#pragma unroll
        for (int ng = 0; ng < 2; ng++) {
            uint32_t bo = (uint32_t)((warp_n * 32 + ng * 16 + b_row) * 80 + kt * 32 + b_byte);
            uint32_t bh[4], bl[4];
            ldsm4(bh, Bh + bo);
            ldsm4(bl, Bl + bo);
#pragma unroll
            for (int mt = 0; mt < 2; mt++) {
                mma_bf16(acc[mt][ng * 2 + 0], ah[mt], bh);
                mma_bf16(acc[mt][ng * 2 + 1], ah[mt], bh + 2);
            }
#pragma unroll
            for (int mt = 0; mt < 2; mt++) {
                mma_bf16(acc[mt][ng * 2 + 0], ah[mt], bl);
                mma_bf16(acc[mt][ng * 2 + 1], ah[mt], bl + 2);
            }
#pragma unroll
            for (int mt = 0; mt < 2; mt++) {
                mma_bf16(acc[mt][ng * 2 + 0], al[mt], bh);
                mma_bf16(acc[mt][ng * 2 + 1], al[mt], bh + 2);
            }
        }
    }
}

// ---------------- prep: split + pack weights into chunk images ---------------
#define NPI (128 * 64)
#define NPC (10 * 128 * 1152)
#define NPE (10 * 128 * 128)
#define PREP_TOTAL (NPI + NPC + NPE)

__global__ void prep_kernel(const float* __restrict__ in_proj_W,
                            const float* __restrict__ conv_W,
                            const float* __restrict__ emb_W) {
    int i = blockIdx.x * blockDim.x + threadIdx.x;
    float val; int tile, j, kr;
    __nv_bfloat16 *WH, *WL;
    if (i < NPI) {
        j = i >> 6; int k = i & 63;
        tile = k >> 5; kr = k & 31;
        val = (k < 40) ? in_proj_W[j * 40 + k] : 0.f;
        WH = WIH; WL = WIL;
    } else if (i < NPI + NPC) {
        int r = i - NPI;
        int d = r / 147456;
        int rr = r % 147456;
        j = rr / 1152;
        int k = rr % 1152;
        tile = d * 36 + (k >> 5); kr = k & 31;
        val = conv_W[r];
        WH = WCH; WL = WCL;
    } else if (i < PREP_TOTAL) {
        int r = i - NPI - NPC;
        int d = r / 16384;
        int rr = r % 16384;
        j = rr >> 7;
        int k = rr & 127;
        tile = d * 4 + (k >> 5); kr = k & 31;
        val = emb_W[r];
        WH = WEH; WL = WEL;
    } else return;
    __nv_bfloat16 hi = __float2bfloat16_rn(val);
    __nv_bfloat16 lo = __float2bfloat16_rn(val - __bfloat162float(hi));
    size_t idx = ((size_t)tile * 128 + j) * 32 + kr;
    WH[idx] = hi;
    WL[idx] = lo;
}

// ---------------- positional encoding ---------------------------------------
__global__ void posenc_kernel(const float* __restrict__ feats) {
    int i = blockIdx.x * blockDim.x + threadIdx.x;
    if (i >= TOTAL * XCOLS) return;
    int node = i / XCOLS, c = i % XCOLS;
    float v = 0.f;
    if (c < 40) {
        int d = 0;
        while (node >= c_off[d + 1]) d++;
        int local = node - c_off[d];
        if (c == 0) {
            v = feats[node];
        } else {
            unsigned ix = mi_deinterleave((unsigned)local);
            unsigned iy = mi_deinterleave((unsigned)local >> 1);
            float inv = 1.f / (float)(1 << d);
            float px = ((float)ix + 0.5f) * inv;
            float py = ((float)iy + 0.5f) * inv;
            float pd = (float)d * (1.f / 9.f);
            if (c == 1)      v = px;
            else if (c == 2) v = py;
            else if (c == 3) v = pd;
            else {
                int e = c - 4;
                int dim = e / 12, rem = e % 12;
                int f = rem % 6;
                float p = (dim == 0) ? px : (dim == 1) ? py : pd;
                float t = p * (float)(1 << f);
                float tr = t - rintf(t);
                v = (rem >= 6) ? cospif(2.f * tr) : sinpif(2.f * tr);
            }
        }
    }
    XBUF[i] = v;
}

// ---------------- pooling d9 -> d8 ------------------------------------------
__global__ void pool9_kernel() {
    int u = blockIdx.x * blockDim.x + threadIdx.x;
    if (u >= 65536 * 32) return;
    int p = u >> 5, c4 = (u & 31) * 4;
    const float* s = HBUF + (size_t)(OFF9 + p * 4) * 128 + c4;
    float4 s0 = *(const float4*)(s);
    float4 s1 = *(const float4*)(s + 128);
    float4 s2 = *(const float4*)(s + 256);
    float4 s3 = *(const float4*)(s + 384);
    float* dp = HBUF + (size_t)(21845 + p) * 128 + c4;
    float4 d0 = *(float4*)dp;
    d0.x += 0.25f * (s0.x + s1.x + s2.x + s3.x);
    d0.y += 0.25f * (s0.y + s1.y + s2.y + s3.y);
    d0.z += 0.25f * (s0.z + s1.z + s2.z + s3.z);
    d0.w += 0.25f * (s0.w + s1.w + s2.w + s3.w);
    *(float4*)dp = d0;
}

// ---------------- in_proj: XBUF[N,48] @ W^T -> HBUF --------------------------
__global__ __launch_bounds__(256, 2)
void inproj_mma(const float* __restrict__ bias) {
    extern __shared__ char dsm[];
    int t = threadIdx.x, lane = t & 31, wid = t >> 5;
    int warp_m = wid >> 2, warp_n = wid & 3;
    int base = blockIdx.x * 64;
    uint32_t sb0 = smem_u32(dsm);
    int a_row = (lane & 7) + ((lane >> 3) & 1) * 8, a_byte = (lane >> 4) * 16;
    int b_row = (lane & 7) + ((lane >> 4) & 1) * 8, b_byte = ((lane >> 3) & 1) * 16;
    int arow = t >> 2, kq = t & 3;
    int bj = t >> 1, bhalf = t & 1;

    float acc[2][4][4];
#pragma unroll
    for (int a = 0; a < 2; a++)
#pragma unroll
        for (int b = 0; b < 4; b++)
#pragma unroll
            for (int c = 0; c < 4; c++) acc[a][b][c] = 0.f;

    float4 pa0, pa1;
    uint4 pbh0, pbh1, pbl0, pbl1;

    auto loadc = [&](int c) {
        int node = base + arow;
        int k0 = c * 32 + kq * 8;
        pa0 = make_float4(0.f, 0.f, 0.f, 0.f); pa1 = pa0;
        if (node < TOTAL && k0 < XCOLS) {
            const float* s = &XBUF[(size_t)node * XCOLS + k0];
            pa0 = *(const float4*)s;
            pa1 = *(const float4*)(s + 4);
        }
        size_t bi = ((size_t)c * 128 + bj) * 32;
        const uint4* gh = (const uint4*)(WIH + bi);
        const uint4* gl = (const uint4*)(WIL + bi);
        pbh0 = gh[bhalf * 2]; pbh1 = gh[bhalf * 2 + 1];
        pbl0 = gl[bhalf * 2]; pbl1 = gl[bhalf * 2 + 1];
    };
    auto storec = [&](int buf) {
        char* B = dsm + buf * BUFB;
        split_store(B, B + 5120, arow * 80 + kq * 16, pa0, pa1);
        int bo = 10240 + bj * 80 + bhalf * 32;
        *(uint4*)(B + bo) = pbh0;
        *(uint4*)(B + bo + 16) = pbh1;
        *(uint4*)(B + bo + 10240) = pbl0;
        *(uint4*)(B + bo + 10240 + 16) = pbl1;
    };

    loadc(0);
    for (int c = 0; c < 2; c++) {
        storec(c & 1);
        __syncthreads();
        if (c + 1 < 2) loadc(c + 1);
        compute_chunk(sb0 + (c & 1) * BUFB, warp_m, warp_n, a_row, a_byte, b_row, b_byte, acc);
        if (c + 1 < 2) __syncthreads();
    }

#pragma unroll
    for (int mt = 0; mt < 2; mt++)
#pragma unroll
        for (int nt = 0; nt < 4; nt++) {
            int col = warp_n * 32 + nt * 8 + (lane & 3) * 2;
            float b0v = bias[col], b1v = bias[col + 1];
            int r0 = base + warp_m * 32 + mt * 16 + (lane >> 2);
            if (r0 < TOTAL)
                *(float2*)&HBUF[(size_t)r0 * 128 + col] =
                    make_float2(acc[mt][nt][0] + b0v, acc[mt][nt][1] + b1v);
            if (r0 + 8 < TOTAL)
                *(float2*)&HBUF[(size_t)(r0 + 8) * 128 + col] =
                    make_float2(acc[mt][nt][2] + b0v, acc[mt][nt][3] + b1v);
        }
}

// ---------------- quadconv: implicit GEMM + fused pooling --------------------
__global__ __launch_bounds__(256, 2)
void conv_mma(int depth, int off, int off_prev, int N, const float* __restrict__ conv_b) {
    extern __shared__ char dsm[];
    __shared__ int nbs[9 * 64];
    int t = threadIdx.x, lane = t & 31, wid = t >> 5;
    int warp_m = wid >> 2, warp_n = wid & 3;
    int base = blockIdx.x * 64;
    int res = 1 << depth;

    for (int e = t; e < 9 * 64; e += 256) {
        int m = e >> 6, r = e & 63;
        int node = base + r;
        int val = -1;
        if (node < N) {
            unsigned ix = mi_deinterleave((unsigned)node);
            unsigned iy = mi_deinterleave((unsigned)node >> 1);
            int dx = m % 3 - 1, dy = m / 3 - 1;
            int nx = (int)ix + dx, ny = (int)iy + dy;
            if (nx >= 0 && nx < res && ny >= 0 && ny < res)
                val = (int)(mi_interleave((unsigned)nx) | (mi_interleave((unsigned)ny) << 1));
        }
        nbs[m * 64 + r] = val;
    }
    __syncthreads();

    uint32_t sb0 = smem_u32(dsm);
    int a_row = (lane & 7) + ((lane >> 3) & 1) * 8, a_byte = (lane >> 4) * 16;
    int b_row = (lane & 7) + ((lane >> 4) & 1) * 8, b_byte = ((lane >> 3) & 1) * 16;
    int arow = t >> 2, kq = t & 3;
    int bj = t >> 1, bhalf = t & 1;
    int tbase = depth * 36;

    float acc[2][4][4];
#pragma unroll
    for (int a = 0; a < 2; a++)
#pragma unroll
        for (int b = 0; b < 4; b++)
#pragma unroll
            for (int c = 0; c < 4; c++) acc[a][b][c] = 0.f;

    float4 pa0, pa1;
    uint4 pbh0, pbh1, pbl0, pbl1;

    auto loadc = [&](int c) {
        int m = c >> 2, c0 = (c & 3) * 32;
        int nbi = nbs[m * 64 + arow];
        pa0 = make_float4(0.f, 0.f, 0.f, 0.f); pa1 = pa0;
        if (nbi >= 0) {
            const float* s = &HBUF[(size_t)(off + nbi) * 128 + c0 + kq * 8];
            pa0 = *(const float4*)s;
            pa1 = *(const float4*)(s + 4);
        }
        size_t bi = ((size_t)(tbase + c) * 128 + bj) * 32;
        const uint4* gh = (const uint4*)(WCH + bi);
        const uint4* gl = (const uint4*)(WCL + bi);
        pbh0 = gh[bhalf * 2]; pbh1 = gh[bhalf * 2 + 1];
        pbl0 = gl[bhalf * 2]; pbl1 = gl[bhalf * 2 + 1];
    };
    auto storec = [&](int buf) {
        char* B = dsm + buf * BUFB;
        split_store(B, B + 5120, arow * 80 + kq * 16, pa0, pa1);
        int bo = 10240 + bj * 80 + bhalf * 32;
        *(uint4*)(B + bo) = pbh0;
        *(uint4*)(B + bo + 16) = pbh1;
        *(uint4*)(B + bo + 10240) = pbl0;
        *(uint4*)(B + bo + 10240 + 16) = pbl1;
    };

    loadc(0);
    for (int c = 0; c < 36; c++) {
        storec(c & 1);
        __syncthreads();
        if (c + 1 < 36) loadc(c + 1);
        compute_chunk(sb0 + (c & 1) * BUFB, warp_m, warp_n, a_row, a_byte, b_row, b_byte, acc);
        if (c + 1 < 36) __syncthreads();
    }

    // epilogue: bias + relu, store, fused quad pooling via shuffles
#pragma unroll
    for (int mt = 0; mt < 2; mt++)
#pragma unroll
        for (int nt = 0; nt < 4; nt++) {
            int col = warp_n * 32 + nt * 8 + (lane & 3) * 2;
            float b0v = conv_b[depth * 128 + col], b1v = conv_b[depth * 128 + col + 1];
            int rl = warp_m * 32 + mt * 16 + (lane >> 2);
            float v00 = fmaxf(acc[mt][nt][0] + b0v, 0.f);
            float v01 = fmaxf(acc[mt][nt][1] + b1v, 0.f);
            float v10 = fmaxf(acc[mt][nt][2] + b0v, 0.f);
            float v11 = fmaxf(acc[mt][nt][3] + b1v, 0.f);
            if (base + rl < N)
                *(float2*)&HCBUF[(size_t)(off + base + rl) * 128 + col] = make_float2(v00, v01);
            if (base + rl + 8 < N)
                *(float2*)&HCBUF[(size_t)(off + base + rl + 8) * 128 + col] = make_float2(v10, v11);
            // quad sums: rows differ in bits 2..3 of lane
            float s00 = v00; s00 += __shfl_xor_sync(~0u, s00, 4); s00 += __shfl_xor_sync(~0u, s00, 8);
            float s01 = v01; s01 += __shfl_xor_sync(~0u, s01, 4); s01 += __shfl_xor_sync(~0u, s01, 8);
            float s10 = v10; s10 += __shfl_xor_sync(~0u, s10, 4); s10 += __shfl_xor_sync(~0u, s10, 8);
            float s11 = v11; s11 += __shfl_xor_sync(~0u, s11, 4); s11 += __shfl_xor_sync(~0u, s11, 8);
            if ((lane & 12) == 0) {
                int q0 = base + rl;          // multiple of 4
                if (q0 + 3 < N) {
                    float2* dp = (float2*)&HBUF[(size_t)(off_prev + (q0 >> 2)) * 128 + col];
                    float2 cur = *dp;
                    cur.x += 0.25f * s00; cur.y += 0.25f * s01;
                    *dp = cur;
                }
                int q1 = q0 + 8;
                if (q1 + 3 < N) {
                    float2* dp = (float2*)&HBUF[(size_t)(off_prev + (q1 >> 2)) * 128 + col];
                    float2 cur = *dp;
                    cur.x += 0.25f * s10; cur.y += 0.25f * s11;
                    *dp = cur;
                }
            }
        }
}

// ---------------- emb GEMM + fused LayerNorm, all depths ---------------------
__global__ __launch_bounds__(256, 2)
void emb_mma(const float* __restrict__ emb_b,
             const float* __restrict__ ln_g,
             const float* __restrict__ ln_b,
             const float* __restrict__ gain_all,
             float* __restrict__ out) {
    extern __shared__ char dsm[];
    int t = threadIdx.x, lane = t & 31, wid = t >> 5;
    int warp_m = wid >> 2, warp_n = wid & 3;
    int b = blockIdx.x;
    int depth = 0;
    while (b >= c_embcum[depth + 1]) depth++;
    int base = (b - c_embcum[depth]) * 64;
    int off = c_off[depth];
    int N = c_off[depth + 1] - off;
    const float* src = (depth >= 1 && depth <= 8) ? HCBUF : HBUF;

    uint32_t sb0 = smem_u32(dsm);
    int a_row = (lane & 7) + ((lane >> 3) & 1) * 8, a_byte = (lane >> 4) * 16;
    int b_row = (lane & 7) + ((lane >> 4) & 1) * 8, b_byte = ((lane >> 3) & 1) * 16;
    int arow = t >> 2, kq = t & 3;
    int bj = t >> 1, bhalf = t & 1;
    int tbase = depth * 4;

    float acc[2][4][4];
#pragma unroll
    for (int a = 0; a < 2; a++)
#pragma unroll
        for (int bb = 0; bb < 4; bb++)
#pragma unroll
            for (int c = 0; c < 4; c++) acc[a][bb][c] = 0.f;

    float4 pa0, pa1;
    uint4 pbh0, pbh1, pbl0, pbl1;

    auto loadc = [&](int c) {
        int node = base + arow;
        pa0 = make_float4(0.f, 0.f, 0.f, 0.f); pa1 = pa0;
        if (node < N) {
            const float* s = &src[(size_t)(off + node) * 128 + c * 32 + kq * 8];
            pa0 = *(const float4*)s;
            pa1 = *(const float4*)(s + 4);
        }
        size_t bi = ((size_t)(tbase + c) * 128 + bj) * 32;
        const uint4* gh = (const uint4*)(WEH + bi);
        const uint4* gl = (const uint4*)(WEL + bi);
        pbh0 = gh[bhalf * 2]; pbh1 = gh[bhalf * 2 + 1];
        pbl0 = gl[bhalf * 2]; pbl1 = gl[bhalf * 2 + 1];
    };
    auto storec = [&](int buf) {
        char* B = dsm + buf * BUFB;
        split_store(B, B + 5120, arow * 80 + kq * 16, pa0, pa1);
        int bo = 10240 + bj * 80 + bhalf * 32;
        *(uint4*)(B + bo) = pbh0;
        *(uint4*)(B + bo + 16) = pbh1;
        *(uint4*)(B + bo + 10240) = pbl0;
        *(uint4*)(B + bo + 10240 + 16) = pbl1;
    };

    loadc(0);
    for (int c = 0; c < 4; c++) {
        storec(c & 1);
        __syncthreads();
        if (c + 1 < 4) loadc(c + 1);
        compute_chunk(sb0 + (c & 1) * BUFB, warp_m, warp_n, a_row, a_byte, b_row, b_byte, acc);
        __syncthreads();
    }

    // dump accumulators to smem [64][132]
    float* C = (float*)dsm;
#pragma unroll
    for (int mt = 0; mt < 2; mt++)
#pragma unroll
        for (int nt = 0; nt < 4; nt++) {
            int rl = warp_m * 32 + mt * 16 + (lane >> 2);
            int col = warp_n * 32 + nt * 8 + (lane & 3) * 2;
            C[rl * 132 + col] = acc[mt][nt][0];
            C[rl * 132 + col + 1] = acc[mt][nt][1];
            C[(rl + 8) * 132 + col] = acc[mt][nt][2];
            C[(rl + 8) * 132 + col + 1] = acc[mt][nt][3];
        }
    __syncthreads();

    // LayerNorm: thread owns (row = t>>2, 32-col segment = t&3)
    int row = t >> 2, seg = t & 3;
    float z[32];
    const float* ebp = &emb_b[depth * 128 + seg * 32];
    float s = 0.f;
#pragma unroll
    for (int i = 0; i < 32; i++) {
        z[i] = C[row * 132 + seg * 32 + i] + ebp[i];
        s += z[i];
    }
    s += __shfl_xor_sync(~0u, s, 1);
    s += __shfl_xor_sync(~0u, s, 2);
    float mu = s * (1.f / 128.f);
    float q = 0.f;
#pragma unroll
    for (int i = 0; i < 32; i++) { z[i] -= mu; q += z[i] * z[i]; }
    q += __shfl_xor_sync(~0u, q, 1);
    q += __shfl_xor_sync(~0u, q, 2);
    float rs = rsqrtf(q * (1.f / 128.f) + 1e-5f);
    if (base + row < N) {
        const float* lgp = &ln_g[depth * 128 + seg * 32];
        const float* lbp = &ln_b[depth * 128 + seg * 32];
        float gain = gain_all[depth];
        float* dst = &out[(size_t)(off + base + row) * 128 + seg * 32];
#pragma unroll
        for (int i = 0; i < 32; i += 4) {
            float4 o;
            o.x = gain * (z[i] * rs * lgp[i] + lbp[i]);
            o.y = gain * (z[i + 1] * rs * lgp[i + 1] + lbp[i + 1]);
            o.z = gain * (z[i + 2] * rs * lgp[i + 2] + lbp[i + 2]);
            o.w = gain * (z[i + 3] * rs * lgp[i + 3] + lbp[i + 3]);
            *(float4*)(dst + i) = o;
        }
    }
}

// ---------------------------------------------------------------------------
extern "C" void kernel_launch(void* const* d_in, const int* in_sizes, int n_in,
                              void* d_out, int out_size) {
    const float* feats     = (const float*)d_in[0];
    const float* in_proj_W = (const float*)d_in[1];
    const float* in_proj_b = (const float*)d_in[2];
    const float* conv_W    = (const float*)d_in[3];
    const float* conv_b    = (const float*)d_in[4];
    const float* emb_W     = (const float*)d_in[5];
    const float* emb_b     = (const float*)d_in[6];
    const float* ln_g      = (const float*)d_in[7];
    const float* ln_b      = (const float*)d_in[8];
    const float* gain      = (const float*)d_in[9];
    float* out = (float*)d_out;

    // unconditional (no static guards): idempotent, not a stream op
    cudaFuncSetAttribute(inproj_mma, cudaFuncAttributeMaxDynamicSharedMemorySize, DSM_BYTES);
    cudaFuncSetAttribute(conv_mma, cudaFuncAttributeMaxDynamicSharedMemorySize, DSM_BYTES);
    cudaFuncSetAttribute(emb_mma, cudaFuncAttributeMaxDynamicSharedMemorySize, DSM_BYTES);

    prep_kernel<<<(PREP_TOTAL + 255) / 256, 256>>>(in_proj_W, conv_W, emb_W);
    posenc_kernel<<<(TOTAL * XCOLS + 255) / 256, 256>>>(feats);
    inproj_mma<<<(TOTAL + 63) / 64, 256, DSM_BYTES>>>(in_proj_b);
    pool9_kernel<<<(65536 * 32 + 255) / 256, 256>>>();
    for (int dc = 8; dc >= 1; dc--)
        conv_mma<<<(h_size[dc] + 63) / 64, 256, DSM_BYTES>>>(dc, h_off[dc], h_off[dc - 1],
                                                             h_size[dc], conv_b);
    emb_mma<<<5464, 256, DSM_BYTES>>>(emb_b, ln_g, ln_b, gain, out);
}